// round 2
// baseline (speedup 1.0000x reference)
#include <cuda_runtime.h>
#include <math.h>

#define BSZ 16
#define SEQ 512
#define DM  512
#define NH  8
#define DKH 64
#define MTOT (BSZ*SEQ)        // 8192
#define NEG_INF (__int_as_float(0xff800000))

// ---------------- scratch (static device globals; no allocs allowed) ----------------
__device__ float g_Qh[BSZ*NH*SEQ*DKH];   // [b,h,s,d]
__device__ float g_KT[BSZ*NH*DKH*SEQ];   // [b,h,d,s]  (K transposed)
__device__ float g_Vh[BSZ*NH*SEQ*DKH];   // [b,h,s,d]
__device__ float g_X [MTOT*DM];          // attention output, merged heads
__device__ float g_Y [MTOT*DM];          // pre/post layernorm buffer
__device__ float g_H [MTOT*128];         // interference hidden
__device__ float g_stats[4];             // mean0, inv_std0, mean1, inv_std1

// ---------------- SGEMM: C = A[M,K] * B[N,K]^T + bias, fused epilogues -------------
// MODE 0: plain row-major [M,N]
// MODE 1: head-split [b,h,s,d]
// MODE 2: K-transposed [b,h,d,s]
// MODE 3: plain, C = addsrc + scale[0]*(A*B^T + bias)
template<int MODE>
__global__ __launch_bounds__(256) void sgemm_kernel(
    const float* __restrict__ A, const float* __restrict__ B,
    const float* __restrict__ bias, float* __restrict__ C,
    int M, int N, int K,
    const float* __restrict__ addsrc, const float* __restrict__ scale)
{
    __shared__ float As[16][132];
    __shared__ float Bs[16][68];
    const int tid = threadIdx.x;
    const int tx = tid & 15, ty = tid >> 4;
    const int bm = blockIdx.y * 128, bn = blockIdx.x * 64;
    const int a_row = tid >> 2;            // 0..63
    const int a_col = (tid & 3) << 2;      // 0,4,8,12

    float acc[8][4];
#pragma unroll
    for (int i = 0; i < 8; i++)
#pragma unroll
        for (int j = 0; j < 4; j++) acc[i][j] = 0.f;

    for (int k0 = 0; k0 < K; k0 += 16) {
        float4 av0 = *(const float4*)(A + (size_t)(bm + a_row)      * K + k0 + a_col);
        float4 av1 = *(const float4*)(A + (size_t)(bm + a_row + 64) * K + k0 + a_col);
        float4 bv  = *(const float4*)(B + (size_t)(bn + a_row)      * K + k0 + a_col);
        As[a_col+0][a_row]    = av0.x; As[a_col+1][a_row]    = av0.y;
        As[a_col+2][a_row]    = av0.z; As[a_col+3][a_row]    = av0.w;
        As[a_col+0][a_row+64] = av1.x; As[a_col+1][a_row+64] = av1.y;
        As[a_col+2][a_row+64] = av1.z; As[a_col+3][a_row+64] = av1.w;
        Bs[a_col+0][a_row] = bv.x; Bs[a_col+1][a_row] = bv.y;
        Bs[a_col+2][a_row] = bv.z; Bs[a_col+3][a_row] = bv.w;
        __syncthreads();
#pragma unroll
        for (int kk = 0; kk < 16; kk++) {
            float ar[8], br[4];
#pragma unroll
            for (int i = 0; i < 8; i++) ar[i] = As[kk][ty*8 + i];
#pragma unroll
            for (int j = 0; j < 4; j++) br[j] = Bs[kk][tx*4 + j];
#pragma unroll
            for (int i = 0; i < 8; i++)
#pragma unroll
                for (int j = 0; j < 4; j++)
                    acc[i][j] = fmaf(ar[i], br[j], acc[i][j]);
        }
        __syncthreads();
    }

    float isc = 0.f;
    if (MODE == 3) isc = scale[0];
#pragma unroll
    for (int i = 0; i < 8; i++) {
        int m = bm + ty*8 + i;
#pragma unroll
        for (int j = 0; j < 4; j++) {
            int n = bn + tx*4 + j;
            float v = acc[i][j] + bias[n];
            if (MODE == 0) {
                C[(size_t)m * N + n] = v;
            } else if (MODE == 1) {
                int bb = m >> 9, s = m & 511, hh = n >> 6, d = n & 63;
                C[(((size_t)(bb*NH + hh)) * SEQ + s) * DKH + d] = v;
            } else if (MODE == 2) {
                int bb = m >> 9, s = m & 511, hh = n >> 6, d = n & 63;
                C[(((size_t)(bb*NH + hh)) * DKH + d) * SEQ + s] = v;
            } else {
                C[(size_t)m * N + n] = addsrc[(size_t)m * N + n] + isc * v;
            }
        }
    }
}

// ---------------- global norm01 stats (mean, 1/(std_ddof1 + 1e-6)) -----------------
__global__ void stats_kernel(const int* __restrict__ sgap, const int* __restrict__ pcount)
{
    __shared__ float sh[128];
    float s0 = 0, q0 = 0, s1 = 0, q1 = 0;
    for (int idx = threadIdx.x; idx < MTOT; idx += 1024) {
        float a = (float)sgap[idx];   s0 += a; q0 += a*a;
        float b = (float)pcount[idx]; s1 += b; q1 += b*b;
    }
#pragma unroll
    for (int off = 16; off; off >>= 1) {
        s0 += __shfl_xor_sync(0xffffffffu, s0, off);
        q0 += __shfl_xor_sync(0xffffffffu, q0, off);
        s1 += __shfl_xor_sync(0xffffffffu, s1, off);
        q1 += __shfl_xor_sync(0xffffffffu, q1, off);
    }
    int wd = threadIdx.x >> 5, ln = threadIdx.x & 31;
    if (ln == 0) { sh[wd] = s0; sh[32+wd] = q0; sh[64+wd] = s1; sh[96+wd] = q1; }
    __syncthreads();
    if (threadIdx.x == 0) {
        float S0=0,Q0=0,S1=0,Q1=0;
        for (int i = 0; i < 32; i++) { S0+=sh[i]; Q0+=sh[32+i]; S1+=sh[64+i]; Q1+=sh[96+i]; }
        float n = (float)MTOT;
        float m0 = S0 / n, m1 = S1 / n;
        float v0 = (Q0 - n*m0*m0) / (n - 1.f);
        float v1 = (Q1 - n*m1*m1) / (n - 1.f);
        float sd0 = sqrtf(fmaxf(v0, 0.f)) + 1e-6f;
        float sd1 = sqrtf(fmaxf(v1, 0.f)) + 1e-6f;
        g_stats[0] = m0; g_stats[1] = 1.f / sd0;
        g_stats[2] = m1; g_stats[3] = 1.f / sd1;
    }
}

// ---------------- attention: one block per (b,h), K^T resident in smem -------------
// smem: KT[64][512] | attn[16][512] | q[16][64] | Vc[64][64]  = 184320 B
#define ATT_SMEM ((32768 + 8192 + 1024 + 4096) * 4)

__global__ __launch_bounds__(512, 1) void attn_kernel(const float* __restrict__ gammas)
{
    extern __shared__ float sm[];
    float* KTs   = sm;
    float* attnS = sm + 32768;
    float* qs    = sm + 32768 + 8192;
    float* Vc    = sm + 32768 + 8192 + 1024;

    const int bh = blockIdx.x;
    const int b = bh >> 3, h = bh & 7;
    const int tid = threadIdx.x;
    const int w = tid >> 5, lane = tid & 31;
    const float* KTg = g_KT + (size_t)bh * DKH * SEQ;
    const float* Qg  = g_Qh + (size_t)bh * SEQ * DKH;
    const float* Vg  = g_Vh + (size_t)bh * SEQ * DKH;

    for (int idx = tid; idx < (DKH*SEQ)/4; idx += 512)
        ((float4*)KTs)[idx] = ((const float4*)KTg)[idx];

    float gv = gammas[h];
    float gam = -(fmaxf(gv, 0.f) + log1pf(__expf(-fabsf(gv))));   // -softplus
    __syncthreads();

    for (int wave = 0; wave < 32; wave++) {
        int i = wave * 16 + w;

        if (i > 0) {
            qs[w*64 + lane]      = Qg[(size_t)i*64 + lane];
            qs[w*64 + lane + 32] = Qg[(size_t)i*64 + lane + 32];
            __syncwarp();

            float sc[4][4];
#pragma unroll
            for (int t = 0; t < 4; t++)
#pragma unroll
                for (int l = 0; l < 4; l++) sc[t][l] = NEG_INF;

            const float4* KT4 = (const float4*)KTs;
            const float4* q4p = (const float4*)(qs + w*64);
#pragma unroll
            for (int t = 0; t < 4; t++) {
                int g4 = lane + 32*t;
                int j0 = g4 * 4;
                if (j0 < i) {
                    float ax = 0, ay = 0, az = 0, aw = 0;
#pragma unroll
                    for (int d4 = 0; d4 < 16; d4++) {
                        float4 qv = q4p[d4];
                        float4 k0 = KT4[(d4*4+0)*128 + g4];
                        float4 k1 = KT4[(d4*4+1)*128 + g4];
                        float4 k2 = KT4[(d4*4+2)*128 + g4];
                        float4 k3 = KT4[(d4*4+3)*128 + g4];
                        ax = fmaf(qv.x,k0.x,ax); ay = fmaf(qv.x,k0.y,ay); az = fmaf(qv.x,k0.z,az); aw = fmaf(qv.x,k0.w,aw);
                        ax = fmaf(qv.y,k1.x,ax); ay = fmaf(qv.y,k1.y,ay); az = fmaf(qv.y,k1.z,az); aw = fmaf(qv.y,k1.w,aw);
                        ax = fmaf(qv.z,k2.x,ax); ay = fmaf(qv.z,k2.y,ay); az = fmaf(qv.z,k2.z,az); aw = fmaf(qv.z,k2.w,aw);
                        ax = fmaf(qv.w,k3.x,ax); ay = fmaf(qv.w,k3.y,ay); az = fmaf(qv.w,k3.z,az); aw = fmaf(qv.w,k3.w,aw);
                    }
                    sc[t][0] = ax*0.125f; sc[t][1] = ay*0.125f;
                    sc[t][2] = az*0.125f; sc[t][3] = aw*0.125f;
#pragma unroll
                    for (int l = 0; l < 4; l++) if (j0 + l >= i) sc[t][l] = NEG_INF;
                }
            }

            // softmax 1 (unnormalized e; normalization cancels in suffix ratio)
            float m = NEG_INF;
#pragma unroll
            for (int t = 0; t < 4; t++)
#pragma unroll
                for (int l = 0; l < 4; l++) m = fmaxf(m, sc[t][l]);
#pragma unroll
            for (int off = 16; off; off >>= 1)
                m = fmaxf(m, __shfl_xor_sync(0xffffffffu, m, off));

            float e[4][4], ls[4];
#pragma unroll
            for (int t = 0; t < 4; t++) {
                ls[t] = 0.f;
#pragma unroll
                for (int l = 0; l < 4; l++) { e[t][l] = __expf(sc[t][l] - m); ls[t] += e[t][l]; }
            }
            // warp inclusive scan per 128-wide t-block + cross-block offsets
            float excl[4], tot[4];
#pragma unroll
            for (int t = 0; t < 4; t++) {
                float x = ls[t];
#pragma unroll
                for (int off = 1; off < 32; off <<= 1) {
                    float y = __shfl_up_sync(0xffffffffu, x, off);
                    if (lane >= off) x += y;
                }
                excl[t] = x - ls[t];
                tot[t]  = __shfl_sync(0xffffffffu, x, 31);
            }
            float baseA[4], T = 0.f;
#pragma unroll
            for (int t = 0; t < 4; t++) { baseA[t] = T; T += tot[t]; }
            float invT = 1.f / T;

            // temporal reweight: dist = sqrt(clip(suffixP * (i-j))), s2 = s*clip(exp(dist*gam))
#pragma unroll
            for (int t = 0; t < 4; t++) {
                float run = baseA[t] + excl[t];
#pragma unroll
                for (int l = 0; l < 4; l++) {
                    run += e[t][l];
                    int j = 4*lane + 128*t + l;
                    float suf  = fmaxf(T - run, 0.f);
                    float dist = sqrtf(fmaxf(suf * invT * (float)(i - j), 0.f));
                    float tmp  = __expf(dist * gam);
                    tmp = fminf(fmaxf(tmp, 1e-5f), 1e5f);
                    sc[t][l] = (j < i) ? sc[t][l] * tmp : NEG_INF;
                }
            }

            // softmax 2 -> attn row in smem
            float m2 = NEG_INF;
#pragma unroll
            for (int t = 0; t < 4; t++)
#pragma unroll
                for (int l = 0; l < 4; l++) m2 = fmaxf(m2, sc[t][l]);
#pragma unroll
            for (int off = 16; off; off >>= 1)
                m2 = fmaxf(m2, __shfl_xor_sync(0xffffffffu, m2, off));
            float Z = 0.f;
#pragma unroll
            for (int t = 0; t < 4; t++)
#pragma unroll
                for (int l = 0; l < 4; l++) { e[t][l] = __expf(sc[t][l] - m2); Z += e[t][l]; }
#pragma unroll
            for (int off = 16; off; off >>= 1)
                Z += __shfl_xor_sync(0xffffffffu, Z, off);
            float invZ = 1.f / Z;
            float4* ao = (float4*)attnS;
#pragma unroll
            for (int t = 0; t < 4; t++)
                ao[w*128 + lane + 32*t] =
                    make_float4(e[t][0]*invZ, e[t][1]*invZ, e[t][2]*invZ, e[t][3]*invZ);
            __syncwarp();
        }

        // A @ V with V staged through smem chunks (shared across the 16 rows in flight)
        int nch = (wave*16 + 79) >> 6;
        float accx0 = 0, accy0 = 0, accx1 = 0, accy1 = 0;
        for (int c = 0; c < nch; c++) {
            __syncthreads();
            for (int idx = tid; idx < 1024; idx += 512)
                ((float4*)Vc)[idx] = ((const float4*)(Vg + (size_t)c*4096))[idx];
            __syncthreads();
            int jend = i - c*64; jend = (jend > 64) ? 64 : jend;
            if (jend > 0) {
                const float*  arow = attnS + w*512 + c*64;
                const float2* vc2  = (const float2*)Vc;
                int fullj = jend & ~3;
                for (int j = 0; j < fullj; j += 4) {
                    float4 a4 = *(const float4*)(arow + j);
                    float2 v0 = vc2[(j+0)*32 + lane];
                    float2 v1 = vc2[(j+1)*32 + lane];
                    float2 v2 = vc2[(j+2)*32 + lane];
                    float2 v3 = vc2[(j+3)*32 + lane];
                    accx0 = fmaf(a4.x, v0.x, accx0); accy0 = fmaf(a4.x, v0.y, accy0);
                    accx1 = fmaf(a4.y, v1.x, accx1); accy1 = fmaf(a4.y, v1.y, accy1);
                    accx0 = fmaf(a4.z, v2.x, accx0); accy0 = fmaf(a4.z, v2.y, accy0);
                    accx1 = fmaf(a4.w, v3.x, accx1); accy1 = fmaf(a4.w, v3.y, accy1);
                }
                for (int j = fullj; j < jend; j++) {
                    float a  = arow[j];
                    float2 vv = vc2[j*32 + lane];
                    accx0 = fmaf(a, vv.x, accx0); accy0 = fmaf(a, vv.y, accy0);
                }
            }
        }
        float2 res; res.x = accx0 + accx1; res.y = accy0 + accy1;
        ((float2*)(g_X + ((size_t)(b*SEQ + i)) * DM + h*DKH))[lane] = res;
    }
}

// ---------------- interference hidden layer ----------------------------------------
__global__ __launch_bounds__(256) void hidden_kernel(
    const int* __restrict__ sgap, const int* __restrict__ pcount,
    const float* __restrict__ Wi1, const float* __restrict__ bi1)
{
    int idx = blockIdx.x * 256 + threadIdx.x;     // 8192*128 total
    int r = idx >> 7, mcol = idx & 127;
    float ii0 = 0.5f * (tanhf(((float)sgap[r]   - g_stats[0]) * g_stats[1]) + 1.f);
    float ii1 = 0.5f * (tanhf(((float)pcount[r] - g_stats[2]) * g_stats[3]) + 1.f);
    float hv = ii0 * Wi1[2*mcol] + ii1 * Wi1[2*mcol + 1] + bi1[mcol];
    g_H[idx] = fmaxf(hv, 0.f);
}

// ---------------- layernorm (in place on g_Y) ---------------------------------------
__global__ __launch_bounds__(128) void ln_kernel(
    const float* __restrict__ gw, const float* __restrict__ bw)
{
    int r = blockIdx.x, t = threadIdx.x;
    __shared__ float red[8];
    float4 v = ((const float4*)(g_Y + (size_t)r * DM))[t];
    float s = v.x + v.y + v.z + v.w;
#pragma unroll
    for (int off = 16; off; off >>= 1) s += __shfl_xor_sync(0xffffffffu, s, off);
    int wd = t >> 5, ln = t & 31;
    if (ln == 0) red[wd] = s;
    __syncthreads();
    float mu = (red[0] + red[1] + red[2] + red[3]) * (1.f / 512.f);
    float dx = v.x - mu, dy = v.y - mu, dz = v.z - mu, dw = v.w - mu;
    float ss = dx*dx + dy*dy + dz*dz + dw*dw;
#pragma unroll
    for (int off = 16; off; off >>= 1) ss += __shfl_xor_sync(0xffffffffu, ss, off);
    if (ln == 0) red[4 + wd] = ss;
    __syncthreads();
    float var  = (red[4] + red[5] + red[6] + red[7]) * (1.f / 512.f);
    float rstd = rsqrtf(var + 1e-5f);
    float4 gg = ((const float4*)gw)[t];
    float4 bb = ((const float4*)bw)[t];
    float4 o;
    o.x = dx * rstd * gg.x + bb.x;
    o.y = dy * rstd * gg.y + bb.y;
    o.z = dz * rstd * gg.z + bb.z;
    o.w = dw * rstd * gg.w + bb.w;
    ((float4*)(g_Y + (size_t)r * DM))[t] = o;
}

// ---------------- launcher ----------------------------------------------------------
extern "C" void kernel_launch(void* const* d_in, const int* in_sizes, int n_in,
                              void* d_out, int out_size)
{
    const float* q      = (const float*)d_in[0];
    const float* k      = (const float*)d_in[1];
    const float* v      = (const float*)d_in[2];
    const int*   sgap   = (const int*)d_in[3];
    const int*   pcount = (const int*)d_in[4];
    const float* Wq = (const float*)d_in[5];  const float* bq = (const float*)d_in[6];
    const float* Wk = (const float*)d_in[7];  const float* bk = (const float*)d_in[8];
    const float* Wv = (const float*)d_in[9];  const float* bv = (const float*)d_in[10];
    const float* Wo = (const float*)d_in[11]; const float* bo = (const float*)d_in[12];
    const float* gammas = (const float*)d_in[13];
    const float* ln_g = (const float*)d_in[14]; const float* ln_b = (const float*)d_in[15];
    const float* Wi1 = (const float*)d_in[16];  const float* bi1 = (const float*)d_in[17];
    const float* Wi2 = (const float*)d_in[18];  const float* bi2 = (const float*)d_in[19];
    const float* iscale = (const float*)d_in[20];
    float* out = (float*)d_out;

    float *Qh, *KT, *Vh, *X, *Y, *Hb;
    cudaGetSymbolAddress((void**)&Qh, g_Qh);
    cudaGetSymbolAddress((void**)&KT, g_KT);
    cudaGetSymbolAddress((void**)&Vh, g_Vh);
    cudaGetSymbolAddress((void**)&X,  g_X);
    cudaGetSymbolAddress((void**)&Y,  g_Y);
    cudaGetSymbolAddress((void**)&Hb, g_H);

    cudaFuncSetAttribute(attn_kernel, cudaFuncAttributeMaxDynamicSharedMemorySize, ATT_SMEM);

    dim3 gemm_grid(DM/64, MTOT/128);   // (8, 64)

    // QKV projections with fused head-split / transpose epilogues
    sgemm_kernel<1><<<gemm_grid, 256>>>(q, Wq, bq, Qh, MTOT, DM, DM, nullptr, nullptr);
    sgemm_kernel<2><<<gemm_grid, 256>>>(k, Wk, bk, KT, MTOT, DM, DM, nullptr, nullptr);
    sgemm_kernel<1><<<gemm_grid, 256>>>(v, Wv, bv, Vh, MTOT, DM, DM, nullptr, nullptr);

    // norm01 global stats
    stats_kernel<<<1, 1024>>>(sgap, pcount);

    // attention -> g_X
    attn_kernel<<<BSZ*NH, 512, ATT_SMEM>>>(gammas);

    // interference MLP: hidden -> GEMM (fused X add + iscale) -> g_Y
    hidden_kernel<<<(MTOT*128)/256, 256>>>(sgap, pcount, Wi1, bi1);
    sgemm_kernel<3><<<gemm_grid, 256>>>(Hb, Wi2, bi2, Y, MTOT, DM, 128, X, iscale);

    // layernorm in place
    ln_kernel<<<MTOT, 128>>>(ln_g, ln_b);

    // output projection
    sgemm_kernel<0><<<gemm_grid, 256>>>(Y, Wo, bo, out, MTOT, DM, DM, nullptr, nullptr);
}

// round 4
// speedup vs baseline: 1.4574x; 1.4574x over previous
#include <cuda_runtime.h>
#include <cuda_bf16.h>
#include <math.h>
#include <cstdint>

#define BSZ 16
#define SEQ 512
#define DM  512
#define NH  8
#define DKH 64
#define MTOT (BSZ*SEQ)        // 8192
#define NEG_INF (__int_as_float(0xff800000))

// ===================== scratch (no allocs allowed) =====================
__device__ float g_Qh[BSZ*NH*SEQ*DKH];   // [b,h,s,d]
__device__ float g_KT[BSZ*NH*DKH*SEQ];   // [b,h,d,s]
__device__ float g_Vh[BSZ*NH*SEQ*DKH];   // [b,h,s,d]
__device__ float g_X [MTOT*DM];
__device__ float g_Y [MTOT*DM];
__device__ float g_H [MTOT*128];
__device__ float g_stats[4];
__device__ unsigned char g_Wpk[5u*1024u*1024u];  // bf16 hi/lo weight planes

// ===================== small asm helpers =====================
__device__ __forceinline__ uint32_t smem_to_u32(const void* p) {
    uint32_t a;
    asm("{ .reg .u64 t; cvta.to.shared.u64 t, %1; cvt.u32.u64 %0, t; }" : "=r"(a) : "l"(p));
    return a;
}
__device__ __forceinline__ void ldsm4(uint32_t* r, uint32_t addr) {
    asm volatile("ldmatrix.sync.aligned.m8n8.x4.shared.b16 {%0,%1,%2,%3}, [%4];"
        : "=r"(r[0]), "=r"(r[1]), "=r"(r[2]), "=r"(r[3]) : "r"(addr));
}
__device__ __forceinline__ void mma16816(float* c, const uint32_t* a, const uint32_t* b) {
    asm volatile("mma.sync.aligned.m16n8k16.row.col.f32.bf16.bf16.f32 "
        "{%0,%1,%2,%3}, {%4,%5,%6,%7}, {%8,%9}, {%0,%1,%2,%3};"
        : "+f"(c[0]), "+f"(c[1]), "+f"(c[2]), "+f"(c[3])
        : "r"(a[0]), "r"(a[1]), "r"(a[2]), "r"(a[3]), "r"(b[0]), "r"(b[1]));
}
__device__ __forceinline__ uint32_t pack_hi(float x, float y, float& lx, float& ly) {
    __nv_bfloat162 h = __floats2bfloat162_rn(x, y);
    lx = x - __bfloat162float(h.x);
    ly = y - __bfloat162float(h.y);
    return *reinterpret_cast<uint32_t*>(&h);
}
__device__ __forceinline__ uint32_t pack_lo(float lx, float ly) {
    __nv_bfloat162 l = __floats2bfloat162_rn(lx, ly);
    return *reinterpret_cast<uint32_t*>(&l);
}

// ===================== weight pre-split: fp32 -> bf16 hi plane | lo plane ==========
__global__ __launch_bounds__(256) void wconv_kernel(const float* __restrict__ W,
                                                    unsigned char* __restrict__ dst,
                                                    int K, int NK)
{
    int idx = blockIdx.x * 256 + threadIdx.x;   // one per 2 elements
    int halfK = K >> 1;
    int n = idx / halfK;
    int k = (idx - n * halfK) * 2;
    float x0 = W[(size_t)n * K + k];
    float x1 = W[(size_t)n * K + k + 1];
    float lx, ly;
    uint32_t hp = pack_hi(x0, x1, lx, ly);
    uint32_t lp = pack_lo(lx, ly);
    *(uint32_t*)(dst + (size_t)(n * K + k) * 2)                   = hp;
    *(uint32_t*)(dst + (size_t)NK * 2 + (size_t)(n * K + k) * 2)  = lp;
}

// ===================== tensor-core GEMM via mma.sync (bf16 3-term) =================
// C[M,N] = A[M,K] * W[N,K]^T + bias. MODE 0 plain; 1 head-split; 2 K-transpose;
// 3: C = addsrc + scale[0]*(acc+bias).
// smem: A[2 buf][hi|lo][128][40] bf16 + B same = 81920 bytes. Padded stride 80B.
#define TG2_BUF 20480          // one buffer (hi 10240 + lo 10240)
#define TG2_SMEM 81920

template<int MODE>
__global__ __launch_bounds__(256, 1) void tgemm_kernel(
    const float* __restrict__ A, const unsigned char* __restrict__ Bpk,
    const float* __restrict__ bias, float* __restrict__ C,
    int N, int K, int NK,
    const float* __restrict__ addsrc, const float* __restrict__ scale)
{
    extern __shared__ char sm[];
    const uint32_t sbase = smem_to_u32(sm);
    const int tid = threadIdx.x;
    const int wid = tid >> 5, lane = tid & 31;
    const int bm = blockIdx.y * 128, bn = blockIdx.x * 128;
    const int wm = (wid >> 2) * 64, wn = (wid & 3) * 32;
    const int S = K >> 5;

    const unsigned char* BhiP = Bpk;
    const unsigned char* BloP = Bpk + (size_t)NK * 2;

    const int a_row = tid >> 3, a_q = tid & 7;   // A: 4 iters, +32 rows/iter
    const int b_row = tid >> 2, b_q = tid & 3;   // B: 2 iters, +64 rows/iter

    float4 aL[4];
    uint4  bhL[2], blL[2];
    float  acc[16][4];
#pragma unroll
    for (int i = 0; i < 16; i++)
#pragma unroll
        for (int j = 0; j < 4; j++) acc[i][j] = 0.f;

    // ---- staging helpers (inlined) ----
    auto loadA = [&](int s) {
        int k0 = s * 32;
#pragma unroll
        for (int it = 0; it < 4; it++) {
            int row = a_row + it * 32;
            aL[it] = *(const float4*)(A + (size_t)(bm + row) * K + k0 + a_q * 4);
        }
    };
    auto loadB = [&](int s) {
        int k0 = s * 32;
#pragma unroll
        for (int it = 0; it < 2; it++) {
            int row = b_row + it * 64;
            size_t off = ((size_t)(bn + row) * K + k0 + b_q * 8) * 2;
            bhL[it] = *(const uint4*)(BhiP + off);
            blL[it] = *(const uint4*)(BloP + off);
        }
    };
    auto storeA = [&](int buf) {
        char* base = sm + buf * TG2_BUF;
#pragma unroll
        for (int it = 0; it < 4; it++) {
            int row = a_row + it * 32;
            float l0, l1, l2, l3;
            uint32_t h0 = pack_hi(aL[it].x, aL[it].y, l0, l1);
            uint32_t h1 = pack_hi(aL[it].z, aL[it].w, l2, l3);
            uint2 hp; hp.x = h0; hp.y = h1;
            uint2 lp; lp.x = pack_lo(l0, l1); lp.y = pack_lo(l2, l3);
            *(uint2*)(base + row * 80 + a_q * 8)         = hp;
            *(uint2*)(base + 10240 + row * 80 + a_q * 8) = lp;
        }
    };
    auto storeB = [&](int buf) {
        char* base = sm + 40960 + buf * TG2_BUF;
#pragma unroll
        for (int it = 0; it < 2; it++) {
            int row = b_row + it * 64;
            *(uint4*)(base + row * 80 + b_q * 16)         = bhL[it];
            *(uint4*)(base + 10240 + row * 80 + b_q * 16) = blL[it];
        }
    };

    const int aoff   = (lane & 15) * 80 + (lane >> 4) * 16;
    const int boff_n = ((lane >> 4) << 3) + (lane & 7);
    const int bsel   = ((lane >> 3) & 1) * 16;

    auto compute = [&](int buf) {
        uint32_t Abase = sbase + buf * TG2_BUF;
        uint32_t Bbase = sbase + 40960 + buf * TG2_BUF;
#pragma unroll
        for (int kh = 0; kh < 2; kh++) {
            uint32_t bh[8], bl[8], a[16];
#pragma unroll
            for (int nf2 = 0; nf2 < 2; nf2++) {
                uint32_t baddr = Bbase + (wn + nf2 * 16 + boff_n) * 80 + kh * 32 + bsel;
                ldsm4(bh + nf2 * 4, baddr);
                ldsm4(bl + nf2 * 4, baddr + 10240);
            }
#pragma unroll
            for (int mf = 0; mf < 4; mf++)
                ldsm4(a + mf * 4, Abase + (wm + mf * 16) * 80 + kh * 32 + aoff);
#pragma unroll
            for (int mf = 0; mf < 4; mf++)
#pragma unroll
                for (int nf = 0; nf < 4; nf++)
                    mma16816(acc[mf * 4 + nf], a + mf * 4, bh + nf * 2);
#pragma unroll
            for (int mf = 0; mf < 4; mf++)
#pragma unroll
                for (int nf = 0; nf < 4; nf++)
                    mma16816(acc[mf * 4 + nf], a + mf * 4, bl + nf * 2);
#pragma unroll
            for (int mf = 0; mf < 4; mf++)
                ldsm4(a + mf * 4, Abase + 10240 + (wm + mf * 16) * 80 + kh * 32 + aoff);
#pragma unroll
            for (int mf = 0; mf < 4; mf++)
#pragma unroll
                for (int nf = 0; nf < 4; nf++)
                    mma16816(acc[mf * 4 + nf], a + mf * 4, bh + nf * 2);
        }
    };

    // ---- pipeline ----
    loadA(0); loadB(0);
    storeA(0); storeB(0);
    __syncthreads();
    for (int s = 0; s < S; s++) {
        if (s + 1 < S) { loadA(s + 1); loadB(s + 1); }
        compute(s & 1);
        if (s + 1 < S) {
            storeA((s + 1) & 1); storeB((s + 1) & 1);
            __syncthreads();
        }
    }

    // ---- epilogue ----
    const float isc = (MODE == 3) ? scale[0] : 0.f;
#pragma unroll
    for (int mf = 0; mf < 4; mf++) {
#pragma unroll
        for (int nf = 0; nf < 4; nf++) {
            float* cc = acc[mf * 4 + nf];
            int col = bn + wn + nf * 8 + (lane & 3) * 2;
            float b0 = bias[col], b1 = bias[col + 1];
#pragma unroll
            for (int rp = 0; rp < 2; rp++) {
                int m = bm + wm + mf * 16 + (lane >> 2) + rp * 8;
                float v0 = cc[rp * 2 + 0] + b0;
                float v1 = cc[rp * 2 + 1] + b1;
                if (MODE == 0) {
                    *(float2*)(C + (size_t)m * N + col) = make_float2(v0, v1);
                } else if (MODE == 1) {
                    int bb = m >> 9, si = m & 511, hh = col >> 6, d = col & 63;
                    *(float2*)(C + (((size_t)(bb * NH + hh)) * SEQ + si) * DKH + d) =
                        make_float2(v0, v1);
                } else if (MODE == 2) {
                    int bb = m >> 9, si = m & 511, hh = col >> 6, d = col & 63;
                    float* p = C + (((size_t)(bb * NH + hh)) * DKH + d) * SEQ + si;
                    p[0] = v0; p[SEQ] = v1;
                } else {
                    const float* ad = addsrc + (size_t)m * N + col;
                    *(float2*)(C + (size_t)m * N + col) =
                        make_float2(ad[0] + isc * v0, ad[1] + isc * v1);
                }
            }
        }
    }
}

// ===================== norm01 stats =====================
__global__ void stats_kernel(const int* __restrict__ sgap, const int* __restrict__ pcount)
{
    __shared__ float sh[128];
    float s0 = 0, q0 = 0, s1 = 0, q1 = 0;
    for (int idx = threadIdx.x; idx < MTOT; idx += 1024) {
        float a = (float)sgap[idx];   s0 += a; q0 += a*a;
        float b = (float)pcount[idx]; s1 += b; q1 += b*b;
    }
#pragma unroll
    for (int off = 16; off; off >>= 1) {
        s0 += __shfl_xor_sync(0xffffffffu, s0, off);
        q0 += __shfl_xor_sync(0xffffffffu, q0, off);
        s1 += __shfl_xor_sync(0xffffffffu, s1, off);
        q1 += __shfl_xor_sync(0xffffffffu, q1, off);
    }
    int wd = threadIdx.x >> 5, ln = threadIdx.x & 31;
    if (ln == 0) { sh[wd] = s0; sh[32+wd] = q0; sh[64+wd] = s1; sh[96+wd] = q1; }
    __syncthreads();
    if (threadIdx.x == 0) {
        float S0=0,Q0=0,S1=0,Q1=0;
        for (int i = 0; i < 32; i++) { S0+=sh[i]; Q0+=sh[32+i]; S1+=sh[64+i]; Q1+=sh[96+i]; }
        float n = (float)MTOT;
        float m0 = S0 / n, m1 = S1 / n;
        float v0 = (Q0 - n*m0*m0) / (n - 1.f);
        float v1 = (Q1 - n*m1*m1) / (n - 1.f);
        g_stats[0] = m0; g_stats[1] = 1.f / (sqrtf(fmaxf(v0, 0.f)) + 1e-6f);
        g_stats[2] = m1; g_stats[3] = 1.f / (sqrtf(fmaxf(v1, 0.f)) + 1e-6f);
    }
}

// ===================== attention (unchanged — passed in R2) =====================
#define ATT_SMEM ((32768 + 8192 + 1024 + 4096) * 4)

__global__ __launch_bounds__(512, 1) void attn_kernel(const float* __restrict__ gammas)
{
    extern __shared__ float smf[];
    float* KTs   = smf;
    float* attnS = smf + 32768;
    float* qs    = smf + 32768 + 8192;
    float* Vc    = smf + 32768 + 8192 + 1024;

    const int bh = blockIdx.x;
    const int b = bh >> 3, h = bh & 7;
    const int tid = threadIdx.x;
    const int w = tid >> 5, lane = tid & 31;
    const float* KTg = g_KT + (size_t)bh * DKH * SEQ;
    const float* Qg  = g_Qh + (size_t)bh * SEQ * DKH;
    const float* Vg  = g_Vh + (size_t)bh * SEQ * DKH;

    for (int idx = tid; idx < (DKH*SEQ)/4; idx += 512)
        ((float4*)KTs)[idx] = ((const float4*)KTg)[idx];

    float gv = gammas[h];
    float gam = -(fmaxf(gv, 0.f) + log1pf(__expf(-fabsf(gv))));
    __syncthreads();

    for (int wave = 0; wave < 32; wave++) {
        int i = wave * 16 + w;

        if (i > 0) {
            qs[w*64 + lane]      = Qg[(size_t)i*64 + lane];
            qs[w*64 + lane + 32] = Qg[(size_t)i*64 + lane + 32];
            __syncwarp();

            float sc[4][4];
#pragma unroll
            for (int t = 0; t < 4; t++)
#pragma unroll
                for (int l = 0; l < 4; l++) sc[t][l] = NEG_INF;

            const float4* KT4 = (const float4*)KTs;
            const float4* q4p = (const float4*)(qs + w*64);
#pragma unroll
            for (int t = 0; t < 4; t++) {
                int g4 = lane + 32*t;
                int j0 = g4 * 4;
                if (j0 < i) {
                    float ax = 0, ay = 0, az = 0, aw = 0;
#pragma unroll
                    for (int d4 = 0; d4 < 16; d4++) {
                        float4 qv = q4p[d4];
                        float4 k0 = KT4[(d4*4+0)*128 + g4];
                        float4 k1 = KT4[(d4*4+1)*128 + g4];
                        float4 k2 = KT4[(d4*4+2)*128 + g4];
                        float4 k3 = KT4[(d4*4+3)*128 + g4];
                        ax = fmaf(qv.x,k0.x,ax); ay = fmaf(qv.x,k0.y,ay); az = fmaf(qv.x,k0.z,az); aw = fmaf(qv.x,k0.w,aw);
                        ax = fmaf(qv.y,k1.x,ax); ay = fmaf(qv.y,k1.y,ay); az = fmaf(qv.y,k1.z,az); aw = fmaf(qv.y,k1.w,aw);
                        ax = fmaf(qv.z,k2.x,ax); ay = fmaf(qv.z,k2.y,ay); az = fmaf(qv.z,k2.z,az); aw = fmaf(qv.z,k2.w,aw);
                        ax = fmaf(qv.w,k3.x,ax); ay = fmaf(qv.w,k3.y,ay); az = fmaf(qv.w,k3.z,az); aw = fmaf(qv.w,k3.w,aw);
                    }
                    sc[t][0] = ax*0.125f; sc[t][1] = ay*0.125f;
                    sc[t][2] = az*0.125f; sc[t][3] = aw*0.125f;
#pragma unroll
                    for (int l = 0; l < 4; l++) if (j0 + l >= i) sc[t][l] = NEG_INF;
                }
            }

            float m = NEG_INF;
#pragma unroll
            for (int t = 0; t < 4; t++)
#pragma unroll
                for (int l = 0; l < 4; l++) m = fmaxf(m, sc[t][l]);
#pragma unroll
            for (int off = 16; off; off >>= 1)
                m = fmaxf(m, __shfl_xor_sync(0xffffffffu, m, off));

            float e[4][4], ls[4];
#pragma unroll
            for (int t = 0; t < 4; t++) {
                ls[t] = 0.f;
#pragma unroll
                for (int l = 0; l < 4; l++) { e[t][l] = __expf(sc[t][l] - m); ls[t] += e[t][l]; }
            }
            float excl[4], tot[4];
#pragma unroll
            for (int t = 0; t < 4; t++) {
                float x = ls[t];
#pragma unroll
                for (int off = 1; off < 32; off <<= 1) {
                    float y = __shfl_up_sync(0xffffffffu, x, off);
                    if (lane >= off) x += y;
                }
                excl[t] = x - ls[t];
                tot[t]  = __shfl_sync(0xffffffffu, x, 31);
            }
            float baseA[4], T = 0.f;
#pragma unroll
            for (int t = 0; t < 4; t++) { baseA[t] = T; T += tot[t]; }
            float invT = 1.f / T;

#pragma unroll
            for (int t = 0; t < 4; t++) {
                float run = baseA[t] + excl[t];
#pragma unroll
                for (int l = 0; l < 4; l++) {
                    run += e[t][l];
                    int j = 4*lane + 128*t + l;
                    float suf  = fmaxf(T - run, 0.f);
                    float dist = sqrtf(fmaxf(suf * invT * (float)(i - j), 0.f));
                    float tmp  = __expf(dist * gam);
                    tmp = fminf(fmaxf(tmp, 1e-5f), 1e5f);
                    sc[t][l] = (j < i) ? sc[t][l] * tmp : NEG_INF;
                }
            }

            float m2 = NEG_INF;
#pragma unroll
            for (int t = 0; t < 4; t++)
#pragma unroll
                for (int l = 0; l < 4; l++) m2 = fmaxf(m2, sc[t][l]);
#pragma unroll
            for (int off = 16; off; off >>= 1)
                m2 = fmaxf(m2, __shfl_xor_sync(0xffffffffu, m2, off));
            float Z = 0.f;
#pragma unroll
            for (int t = 0; t < 4; t++)
#pragma unroll
                for (int l = 0; l < 4; l++) { e[t][l] = __expf(sc[t][l] - m2); Z += e[t][l]; }
#pragma unroll
            for (int off = 16; off; off >>= 1)
                Z += __shfl_xor_sync(0xffffffffu, Z, off);
            float invZ = 1.f / Z;
            float4* ao = (float4*)attnS;
#pragma unroll
            for (int t = 0; t < 4; t++)
                ao[w*128 + lane + 32*t] =
                    make_float4(e[t][0]*invZ, e[t][1]*invZ, e[t][2]*invZ, e[t][3]*invZ);
            __syncwarp();
        }

        int nch = (wave*16 + 79) >> 6;
        float accx0 = 0, accy0 = 0, accx1 = 0, accy1 = 0;
        for (int c = 0; c < nch; c++) {
            __syncthreads();
            for (int idx = tid; idx < 1024; idx += 512)
                ((float4*)Vc)[idx] = ((const float4*)(Vg + (size_t)c*4096))[idx];
            __syncthreads();
            int jend = i - c*64; jend = (jend > 64) ? 64 : jend;
            if (jend > 0) {
                const float*  arow = attnS + w*512 + c*64;
                const float2* vc2  = (const float2*)Vc;
                int fullj = jend & ~3;
                for (int j = 0; j < fullj; j += 4) {
                    float4 a4 = *(const float4*)(arow + j);
                    float2 v0 = vc2[(j+0)*32 + lane];
                    float2 v1 = vc2[(j+1)*32 + lane];
                    float2 v2 = vc2[(j+2)*32 + lane];
                    float2 v3 = vc2[(j+3)*32 + lane];
                    accx0 = fmaf(a4.x, v0.x, accx0); accy0 = fmaf(a4.x, v0.y, accy0);
                    accx1 = fmaf(a4.y, v1.x, accx1); accy1 = fmaf(a4.y, v1.y, accy1);
                    accx0 = fmaf(a4.z, v2.x, accx0); accy0 = fmaf(a4.z, v2.y, accy0);
                    accx1 = fmaf(a4.w, v3.x, accx1); accy1 = fmaf(a4.w, v3.y, accy1);
                }
                for (int j = fullj; j < jend; j++) {
                    float a  = arow[j];
                    float2 vv = vc2[j*32 + lane];
                    accx0 = fmaf(a, vv.x, accx0); accy0 = fmaf(a, vv.y, accy0);
                }
            }
        }
        float2 res; res.x = accx0 + accx1; res.y = accy0 + accy1;
        ((float2*)(g_X + ((size_t)(b*SEQ + i)) * DM + h*DKH))[lane] = res;
    }
}

// ===================== interference hidden layer =====================
__global__ __launch_bounds__(256) void hidden_kernel(
    const int* __restrict__ sgap, const int* __restrict__ pcount,
    const float* __restrict__ Wi1, const float* __restrict__ bi1)
{
    int idx = blockIdx.x * 256 + threadIdx.x;
    int r = idx >> 7, mcol = idx & 127;
    float ii0 = 0.5f * (tanhf(((float)sgap[r]   - g_stats[0]) * g_stats[1]) + 1.f);
    float ii1 = 0.5f * (tanhf(((float)pcount[r] - g_stats[2]) * g_stats[3]) + 1.f);
    float hv = ii0 * Wi1[2*mcol] + ii1 * Wi1[2*mcol + 1] + bi1[mcol];
    g_H[idx] = fmaxf(hv, 0.f);
}

// ===================== layernorm =====================
__global__ __launch_bounds__(128) void ln_kernel(
    const float* __restrict__ gw, const float* __restrict__ bw)
{
    int r = blockIdx.x, t = threadIdx.x;
    __shared__ float red[8];
    float4 v = ((const float4*)(g_Y + (size_t)r * DM))[t];
    float s = v.x + v.y + v.z + v.w;
#pragma unroll
    for (int off = 16; off; off >>= 1) s += __shfl_xor_sync(0xffffffffu, s, off);
    int wd = t >> 5, ln = t & 31;
    if (ln == 0) red[wd] = s;
    __syncthreads();
    float mu = (red[0] + red[1] + red[2] + red[3]) * (1.f / 512.f);
    float dx = v.x - mu, dy = v.y - mu, dz = v.z - mu, dw = v.w - mu;
    float ss = dx*dx + dy*dy + dz*dz + dw*dw;
#pragma unroll
    for (int off = 16; off; off >>= 1) ss += __shfl_xor_sync(0xffffffffu, ss, off);
    if (ln == 0) red[4 + wd] = ss;
    __syncthreads();
    float var  = (red[4] + red[5] + red[6] + red[7]) * (1.f / 512.f);
    float rstd = rsqrtf(var + 1e-5f);
    float4 gg = ((const float4*)gw)[t];
    float4 bb = ((const float4*)bw)[t];
    float4 o;
    o.x = dx * rstd * gg.x + bb.x;
    o.y = dy * rstd * gg.y + bb.y;
    o.z = dz * rstd * gg.z + bb.z;
    o.w = dw * rstd * gg.w + bb.w;
    ((float4*)(g_Y + (size_t)r * DM))[t] = o;
}

// ===================== launcher =====================
extern "C" void kernel_launch(void* const* d_in, const int* in_sizes, int n_in,
                              void* d_out, int out_size)
{
    const float* q      = (const float*)d_in[0];
    const float* k      = (const float*)d_in[1];
    const float* v      = (const float*)d_in[2];
    const int*   sgap   = (const int*)d_in[3];
    const int*   pcount = (const int*)d_in[4];
    const float* Wq = (const float*)d_in[5];  const float* bq = (const float*)d_in[6];
    const float* Wk = (const float*)d_in[7];  const float* bk = (const float*)d_in[8];
    const float* Wv = (const float*)d_in[9];  const float* bv = (const float*)d_in[10];
    const float* Wo = (const float*)d_in[11]; const float* bo = (const float*)d_in[12];
    const float* gammas = (const float*)d_in[13];
    const float* ln_g = (const float*)d_in[14]; const float* ln_b = (const float*)d_in[15];
    const float* Wi1 = (const float*)d_in[16];  const float* bi1 = (const float*)d_in[17];
    const float* Wi2 = (const float*)d_in[18];  const float* bi2 = (const float*)d_in[19];
    const float* iscale = (const float*)d_in[20];
    float* out = (float*)d_out;

    float *Qh, *KT, *Vh, *X, *Y, *Hb;
    unsigned char* Wpk;
    cudaGetSymbolAddress((void**)&Qh, g_Qh);
    cudaGetSymbolAddress((void**)&KT, g_KT);
    cudaGetSymbolAddress((void**)&Vh, g_Vh);
    cudaGetSymbolAddress((void**)&X,  g_X);
    cudaGetSymbolAddress((void**)&Y,  g_Y);
    cudaGetSymbolAddress((void**)&Hb, g_H);
    cudaGetSymbolAddress((void**)&Wpk, g_Wpk);

    cudaFuncSetAttribute(attn_kernel, cudaFuncAttributeMaxDynamicSharedMemorySize, ATT_SMEM);
    cudaFuncSetAttribute(tgemm_kernel<0>, cudaFuncAttributeMaxDynamicSharedMemorySize, TG2_SMEM);
    cudaFuncSetAttribute(tgemm_kernel<1>, cudaFuncAttributeMaxDynamicSharedMemorySize, TG2_SMEM);
    cudaFuncSetAttribute(tgemm_kernel<2>, cudaFuncAttributeMaxDynamicSharedMemorySize, TG2_SMEM);
    cudaFuncSetAttribute(tgemm_kernel<3>, cudaFuncAttributeMaxDynamicSharedMemorySize, TG2_SMEM);

    // pre-split weights into bf16 hi/lo planes
    wconv_kernel<<<512, 256>>>(Wq,  Wpk + 0u*1048576u, 512, 512*512);
    wconv_kernel<<<512, 256>>>(Wk,  Wpk + 1u*1048576u, 512, 512*512);
    wconv_kernel<<<512, 256>>>(Wv,  Wpk + 2u*1048576u, 512, 512*512);
    wconv_kernel<<<512, 256>>>(Wo,  Wpk + 3u*1048576u, 512, 512*512);
    wconv_kernel<<<128, 256>>>(Wi2, Wpk + 4u*1048576u, 128, 512*128);

    dim3 gg(4, 64);   // N-tiles(128) x M-tiles(128)

    tgemm_kernel<1><<<gg, 256, TG2_SMEM>>>(q, Wpk + 0u*1048576u, bq, Qh, DM, DM, 512*512, nullptr, nullptr);
    tgemm_kernel<2><<<gg, 256, TG2_SMEM>>>(k, Wpk + 1u*1048576u, bk, KT, DM, DM, 512*512, nullptr, nullptr);
    tgemm_kernel<1><<<gg, 256, TG2_SMEM>>>(v, Wpk + 2u*1048576u, bv, Vh, DM, DM, 512*512, nullptr, nullptr);

    stats_kernel<<<1, 1024>>>(sgap, pcount);

    attn_kernel<<<BSZ*NH, 512, ATT_SMEM>>>(gammas);

    hidden_kernel<<<(MTOT*128)/256, 256>>>(sgap, pcount, Wi1, bi1);
    tgemm_kernel<3><<<gg, 256, TG2_SMEM>>>(Hb, Wpk + 4u*1048576u, bi2, Y, DM, 128, 512*128, X, iscale);

    ln_kernel<<<MTOT, 128>>>(ln_g, ln_b);

    tgemm_kernel<0><<<gg, 256, TG2_SMEM>>>(Y, Wpk + 3u*1048576u, bo, out, DM, DM, 512*512, nullptr, nullptr);
}

// round 5
// speedup vs baseline: 2.8638x; 1.9650x over previous
#include <cuda_runtime.h>
#include <cuda_bf16.h>
#include <math.h>
#include <cstdint>

#define BSZ 16
#define SEQ 512
#define DM  512
#define NH  8
#define DKH 64
#define MTOT (BSZ*SEQ)            // 8192
#define NEG_INF (__int_as_float(0xff800000))
#define QKVPLN (128*512*64)       // 4194304 elements per plane
#define APLN (128u*512u*512u)     // 33554432 elements per plane

// ===================== scratch (device globals; no allocs) =====================
__device__ __nv_bfloat16 g_Qb [2*QKVPLN];   // [b,h,s,d] hi | lo  (scaled by 1/8)
__device__ __nv_bfloat16 g_Kb [2*QKVPLN];   // [b,h,s,d] hi | lo
__device__ __nv_bfloat16 g_Vtb[2*QKVPLN];   // [b,h,d,s] hi | lo
__device__ float         g_S  [APLN];       // scores fp32
__device__ __nv_bfloat16 g_A  [2*APLN];     // attention probs hi | lo
__device__ float g_X [MTOT*DM];
__device__ float g_Y [MTOT*DM];
__device__ float g_H [MTOT*128];
__device__ float g_stats[4];
__device__ unsigned char g_Wpk[5u*1024u*1024u];

// ===================== asm helpers =====================
__device__ __forceinline__ uint32_t smem_to_u32(const void* p) {
    uint32_t a;
    asm("{ .reg .u64 t; cvta.to.shared.u64 t, %1; cvt.u32.u64 %0, t; }" : "=r"(a) : "l"(p));
    return a;
}
__device__ __forceinline__ void ldsm4(uint32_t* r, uint32_t addr) {
    asm volatile("ldmatrix.sync.aligned.m8n8.x4.shared.b16 {%0,%1,%2,%3}, [%4];"
        : "=r"(r[0]), "=r"(r[1]), "=r"(r[2]), "=r"(r[3]) : "r"(addr));
}
__device__ __forceinline__ void mma16816(float* c, const uint32_t* a, const uint32_t* b) {
    asm volatile("mma.sync.aligned.m16n8k16.row.col.f32.bf16.bf16.f32 "
        "{%0,%1,%2,%3}, {%4,%5,%6,%7}, {%8,%9}, {%0,%1,%2,%3};"
        : "+f"(c[0]), "+f"(c[1]), "+f"(c[2]), "+f"(c[3])
        : "r"(a[0]), "r"(a[1]), "r"(a[2]), "r"(a[3]), "r"(b[0]), "r"(b[1]));
}
__device__ __forceinline__ uint32_t pack_hi(float x, float y, float& lx, float& ly) {
    __nv_bfloat162 h = __floats2bfloat162_rn(x, y);
    lx = x - __bfloat162float(h.x);
    ly = y - __bfloat162float(h.y);
    return *reinterpret_cast<uint32_t*>(&h);
}
__device__ __forceinline__ uint32_t pack_lo(float lx, float ly) {
    __nv_bfloat162 l = __floats2bfloat162_rn(lx, ly);
    return *reinterpret_cast<uint32_t*>(&l);
}

// ===================== fused weight pre-split (1 launch, 5 weights) ===============
__global__ __launch_bounds__(256) void wconv_all(
    const float* __restrict__ Wq, const float* __restrict__ Wk,
    const float* __restrict__ Wv, const float* __restrict__ Wo,
    const float* __restrict__ Wi2, unsigned char* __restrict__ dst)
{
    int bb = blockIdx.x;
    const float* W; unsigned char* d; int K;
    if      (bb < 512)  { W = Wq;  d = dst;              K = 512; }
    else if (bb < 1024) { W = Wk;  d = dst + 1048576u;   K = 512; bb -= 512; }
    else if (bb < 1536) { W = Wv;  d = dst + 2097152u;   K = 512; bb -= 1024; }
    else if (bb < 2048) { W = Wo;  d = dst + 3145728u;   K = 512; bb -= 1536; }
    else                { W = Wi2; d = dst + 4194304u;   K = 128; bb -= 2048; }
    int NK = (K == 512) ? 262144 : 65536;
    int idx = bb * 256 + threadIdx.x;
    int halfK = K >> 1;
    int n = idx / halfK;
    int k = (idx - n * halfK) * 2;
    float x0 = W[(size_t)n * K + k];
    float x1 = W[(size_t)n * K + k + 1];
    float lx, ly;
    uint32_t hp = pack_hi(x0, x1, lx, ly);
    uint32_t lp = pack_lo(lx, ly);
    *(uint32_t*)(d + (size_t)(n * K + k) * 2)                  = hp;
    *(uint32_t*)(d + (size_t)NK * 2 + (size_t)(n * K + k) * 2) = lp;
}

// ===================== projection / misc GEMM via mma.sync ========================
// MODE 0: plain fp32 out. MODE 3: C = addsrc + scale[0]*(acc+bias).
// MODE 4: Q planes bf16 hi/lo [b,h,s,d], scaled 1/8.  MODE 5: K planes.
// MODE 6: V^T planes bf16 hi/lo [b,h,d,s].
#define TG2_BUF 20480
#define TG2_SMEM 81920

template<int MODE>
__global__ __launch_bounds__(256, 1) void tgemm_kernel(
    const float* __restrict__ A, const unsigned char* __restrict__ Bpk,
    const float* __restrict__ bias, float* __restrict__ C, __nv_bfloat16* __restrict__ Cb,
    int N, int K, int NK,
    const float* __restrict__ addsrc, const float* __restrict__ scale)
{
    extern __shared__ char sm[];
    const uint32_t sbase = smem_to_u32(sm);
    const int tid = threadIdx.x;
    const int wid = tid >> 5, lane = tid & 31;
    const int bm = blockIdx.y * 128, bn = blockIdx.x * 128;
    const int wm = (wid >> 2) * 64, wn = (wid & 3) * 32;
    const int S = K >> 5;

    const unsigned char* BhiP = Bpk;
    const unsigned char* BloP = Bpk + (size_t)NK * 2;

    const int a_row = tid >> 3, a_q = tid & 7;
    const int b_row = tid >> 2, b_q = tid & 3;

    float4 aL[4];
    uint4  bhL[2], blL[2];
    float  acc[16][4];
#pragma unroll
    for (int i = 0; i < 16; i++)
#pragma unroll
        for (int j = 0; j < 4; j++) acc[i][j] = 0.f;

    auto loadA = [&](int s) {
        int k0 = s * 32;
#pragma unroll
        for (int it = 0; it < 4; it++)
            aL[it] = *(const float4*)(A + (size_t)(bm + a_row + it*32) * K + k0 + a_q * 4);
    };
    auto loadB = [&](int s) {
        int k0 = s * 32;
#pragma unroll
        for (int it = 0; it < 2; it++) {
            size_t off = ((size_t)(bn + b_row + it*64) * K + k0 + b_q * 8) * 2;
            bhL[it] = *(const uint4*)(BhiP + off);
            blL[it] = *(const uint4*)(BloP + off);
        }
    };
    auto storeA = [&](int buf) {
        char* base = sm + buf * TG2_BUF;
#pragma unroll
        for (int it = 0; it < 4; it++) {
            int row = a_row + it * 32;
            float l0, l1, l2, l3;
            uint2 hp; hp.x = pack_hi(aL[it].x, aL[it].y, l0, l1);
                      hp.y = pack_hi(aL[it].z, aL[it].w, l2, l3);
            uint2 lp; lp.x = pack_lo(l0, l1); lp.y = pack_lo(l2, l3);
            *(uint2*)(base + row * 80 + a_q * 8)         = hp;
            *(uint2*)(base + 10240 + row * 80 + a_q * 8) = lp;
        }
    };
    auto storeB = [&](int buf) {
        char* base = sm + 40960 + buf * TG2_BUF;
#pragma unroll
        for (int it = 0; it < 2; it++) {
            int row = b_row + it * 64;
            *(uint4*)(base + row * 80 + b_q * 16)         = bhL[it];
            *(uint4*)(base + 10240 + row * 80 + b_q * 16) = blL[it];
        }
    };

    const int aoff   = (lane & 15) * 80 + (lane >> 4) * 16;
    const int boff_n = ((lane >> 4) << 3) + (lane & 7);
    const int bsel   = ((lane >> 3) & 1) * 16;

    auto compute = [&](int buf) {
        uint32_t Abase = sbase + buf * TG2_BUF;
        uint32_t Bbase = sbase + 40960 + buf * TG2_BUF;
#pragma unroll
        for (int kh = 0; kh < 2; kh++) {
            uint32_t bh[8], bl[8], a[16];
#pragma unroll
            for (int nf2 = 0; nf2 < 2; nf2++) {
                uint32_t baddr = Bbase + (wn + nf2 * 16 + boff_n) * 80 + kh * 32 + bsel;
                ldsm4(bh + nf2 * 4, baddr);
                ldsm4(bl + nf2 * 4, baddr + 10240);
            }
#pragma unroll
            for (int mf = 0; mf < 4; mf++)
                ldsm4(a + mf * 4, Abase + (wm + mf * 16) * 80 + kh * 32 + aoff);
#pragma unroll
            for (int mf = 0; mf < 4; mf++)
#pragma unroll
                for (int nf = 0; nf < 4; nf++)
                    mma16816(acc[mf * 4 + nf], a + mf * 4, bh + nf * 2);
#pragma unroll
            for (int mf = 0; mf < 4; mf++)
#pragma unroll
                for (int nf = 0; nf < 4; nf++)
                    mma16816(acc[mf * 4 + nf], a + mf * 4, bl + nf * 2);
#pragma unroll
            for (int mf = 0; mf < 4; mf++)
                ldsm4(a + mf * 4, Abase + 10240 + (wm + mf * 16) * 80 + kh * 32 + aoff);
#pragma unroll
            for (int mf = 0; mf < 4; mf++)
#pragma unroll
                for (int nf = 0; nf < 4; nf++)
                    mma16816(acc[mf * 4 + nf], a + mf * 4, bh + nf * 2);
        }
    };

    loadA(0); loadB(0);
    storeA(0); storeB(0);
    __syncthreads();
    for (int s = 0; s < S; s++) {
        if (s + 1 < S) { loadA(s + 1); loadB(s + 1); }
        compute(s & 1);
        if (s + 1 < S) {
            storeA((s + 1) & 1); storeB((s + 1) & 1);
            __syncthreads();
        }
    }

    const float isc = (MODE == 3) ? scale[0] : 0.f;
#pragma unroll
    for (int mf = 0; mf < 4; mf++) {
#pragma unroll
        for (int nf = 0; nf < 4; nf++) {
            float* cc = acc[mf * 4 + nf];
            int col = bn + wn + nf * 8 + (lane & 3) * 2;
            float b0 = bias[col], b1 = bias[col + 1];
#pragma unroll
            for (int rp = 0; rp < 2; rp++) {
                int m = bm + wm + mf * 16 + (lane >> 2) + rp * 8;
                float v0 = cc[rp * 2 + 0] + b0;
                float v1 = cc[rp * 2 + 1] + b1;
                if (MODE == 0) {
                    *(float2*)(C + (size_t)m * N + col) = make_float2(v0, v1);
                } else if (MODE == 3) {
                    const float* ad = addsrc + (size_t)m * N + col;
                    *(float2*)(C + (size_t)m * N + col) =
                        make_float2(ad[0] + isc * v0, ad[1] + isc * v1);
                } else if (MODE == 4 || MODE == 5) {
                    if (MODE == 4) { v0 *= 0.125f; v1 *= 0.125f; }
                    int bb = m >> 9, si = m & 511, hh = col >> 6, d = col & 63;
                    size_t idx = (((size_t)(bb * NH + hh)) * SEQ + si) * DKH + d;
                    float l0, l1;
                    uint32_t hp = pack_hi(v0, v1, l0, l1);
                    uint32_t lp = pack_lo(l0, l1);
                    *(uint32_t*)&Cb[idx]          = hp;
                    *(uint32_t*)&Cb[idx + QKVPLN] = lp;
                } else {  // MODE 6: V^T planes
                    int bb = m >> 9, si = m & 511, hh = col >> 6, d = col & 63;
                    size_t i0 = (((size_t)(bb * NH + hh)) * DKH + d) * SEQ + si;
                    __nv_bfloat16 h0 = __float2bfloat16(v0);
                    __nv_bfloat16 h1 = __float2bfloat16(v1);
                    Cb[i0]                = h0;
                    Cb[i0 + QKVPLN]       = __float2bfloat16(v0 - __bfloat162float(h0));
                    Cb[i0 + SEQ]          = h1;
                    Cb[i0 + SEQ + QKVPLN] = __float2bfloat16(v1 - __bfloat162float(h1));
                }
            }
        }
    }
}

// ===================== QK^T batched GEMM (causal tile skip) ========================
// grid (4 colT, 4 rowT, 128 bh); tile 128x128, K=64 single load; smem 72KB.
#define SK_SMEM 73728

__global__ __launch_bounds__(256, 1) void qk_kernel()
{
    if (blockIdx.x > blockIdx.y) return;   // fully-masked tile
    extern __shared__ char sm[];
    const uint32_t sbase = smem_to_u32(sm);
    const int bn = blockIdx.x * 128, bm = blockIdx.y * 128;
    const int bh = blockIdx.z;
    const int tid = threadIdx.x, wid = tid >> 5, lane = tid & 31;

#pragma unroll
    for (int pl = 0; pl < 2; pl++) {
        const uint4* qsrc = (const uint4*)(g_Qb + (size_t)pl * QKVPLN + ((size_t)bh * 512 + bm) * 64);
        const uint4* ksrc = (const uint4*)(g_Kb + (size_t)pl * QKVPLN + ((size_t)bh * 512 + bn) * 64);
        char* qdst = sm + pl * 18432;
        char* kdst = sm + 36864 + pl * 18432;
#pragma unroll
        for (int it = 0; it < 4; it++) {
            int idx = it * 256 + tid;
            int r = idx >> 3, c = idx & 7;
            *(uint4*)(qdst + r * 144 + c * 16) = qsrc[r * 8 + c];
            *(uint4*)(kdst + r * 144 + c * 16) = ksrc[r * 8 + c];
        }
    }
    __syncthreads();

    const int wm = (wid >> 2) * 64, wn = (wid & 3) * 32;
    const int aoff   = (lane & 15) * 144 + (lane >> 4) * 16;
    const int boff_n = ((lane >> 4) << 3) + (lane & 7);
    const int bsel   = ((lane >> 3) & 1) * 16;
    const uint32_t QHI = sbase, QLO = sbase + 18432;
    const uint32_t KHI = sbase + 36864;

    float acc[16][4];
#pragma unroll
    for (int i = 0; i < 16; i++)
#pragma unroll
        for (int j = 0; j < 4; j++) acc[i][j] = 0.f;

#pragma unroll
    for (int kh = 0; kh < 4; kh++) {
        uint32_t bh_[8], bl_[8], a[16];
#pragma unroll
        for (int nf2 = 0; nf2 < 2; nf2++) {
            uint32_t baddr = KHI + (wn + nf2 * 16 + boff_n) * 144 + kh * 32 + bsel;
            ldsm4(bh_ + nf2 * 4, baddr);
            ldsm4(bl_ + nf2 * 4, baddr + 18432);
        }
#pragma unroll
        for (int mf = 0; mf < 4; mf++)
            ldsm4(a + mf * 4, QHI + (wm + mf * 16) * 144 + kh * 32 + aoff);
#pragma unroll
        for (int mf = 0; mf < 4; mf++)
#pragma unroll
            for (int nf = 0; nf < 4; nf++)
                mma16816(acc[mf * 4 + nf], a + mf * 4, bh_ + nf * 2);
#pragma unroll
        for (int mf = 0; mf < 4; mf++)
#pragma unroll
            for (int nf = 0; nf < 4; nf++)
                mma16816(acc[mf * 4 + nf], a + mf * 4, bl_ + nf * 2);
#pragma unroll
        for (int mf = 0; mf < 4; mf++)
            ldsm4(a + mf * 4, QLO + (wm + mf * 16) * 144 + kh * 32 + aoff);
#pragma unroll
        for (int mf = 0; mf < 4; mf++)
#pragma unroll
            for (int nf = 0; nf < 4; nf++)
                mma16816(acc[mf * 4 + nf], a + mf * 4, bh_ + nf * 2);
    }

    float* Sp = g_S + (size_t)bh * 512 * 512;
#pragma unroll
    for (int mf = 0; mf < 4; mf++)
#pragma unroll
        for (int nf = 0; nf < 4; nf++) {
            float* cc = acc[mf * 4 + nf];
            int col = bn + wn + nf * 8 + (lane & 3) * 2;
#pragma unroll
            for (int rp = 0; rp < 2; rp++) {
                int m = bm + wm + mf * 16 + (lane >> 2) + rp * 8;
                *(float2*)(Sp + (size_t)m * 512 + col) =
                    make_float2(cc[rp * 2], cc[rp * 2 + 1]);
            }
        }
}

// ===================== row kernel: softmax + scan + temporal -> A planes ==========
__global__ __launch_bounds__(256) void row_kernel(const float* __restrict__ gammas)
{
    const int bh = blockIdx.y, h = bh & 7;
    const int wid = threadIdx.x >> 5, lane = threadIdx.x & 31;
    const int i = blockIdx.x * 8 + wid;
    __nv_bfloat16* Ahi = g_A + ((size_t)bh * 512 + i) * 512;

    if (i == 0) {
        uint2 z = make_uint2(0u, 0u);
#pragma unroll
        for (int t = 0; t < 4; t++) {
            int j0 = 4 * (lane + 32 * t);
            *(uint2*)(Ahi + j0)        = z;
            *(uint2*)(Ahi + APLN + j0) = z;
        }
        return;
    }

    float gv = gammas[h];
    float gam = -(fmaxf(gv, 0.f) + log1pf(__expf(-fabsf(gv))));

    const float4* Srow = (const float4*)(g_S + ((size_t)bh * 512 + i) * 512);
    float sc[4][4];
#pragma unroll
    for (int t = 0; t < 4; t++) {
        float4 sv = Srow[lane + 32 * t];
        int j0 = 4 * (lane + 32 * t);
        sc[t][0] = (j0 + 0 < i) ? sv.x : NEG_INF;
        sc[t][1] = (j0 + 1 < i) ? sv.y : NEG_INF;
        sc[t][2] = (j0 + 2 < i) ? sv.z : NEG_INF;
        sc[t][3] = (j0 + 3 < i) ? sv.w : NEG_INF;
    }

    // softmax 1 (unnormalized; normalization cancels in suffix ratio)
    float m = NEG_INF;
#pragma unroll
    for (int t = 0; t < 4; t++)
#pragma unroll
        for (int l = 0; l < 4; l++) m = fmaxf(m, sc[t][l]);
#pragma unroll
    for (int off = 16; off; off >>= 1)
        m = fmaxf(m, __shfl_xor_sync(0xffffffffu, m, off));

    float e[4][4], ls[4];
#pragma unroll
    for (int t = 0; t < 4; t++) {
        ls[t] = 0.f;
#pragma unroll
        for (int l = 0; l < 4; l++) { e[t][l] = __expf(sc[t][l] - m); ls[t] += e[t][l]; }
    }
    float excl[4], tot[4];
#pragma unroll
    for (int t = 0; t < 4; t++) {
        float x = ls[t];
#pragma unroll
        for (int off = 1; off < 32; off <<= 1) {
            float y = __shfl_up_sync(0xffffffffu, x, off);
            if (lane >= off) x += y;
        }
        excl[t] = x - ls[t];
        tot[t]  = __shfl_sync(0xffffffffu, x, 31);
    }
    float baseA[4], T = 0.f;
#pragma unroll
    for (int t = 0; t < 4; t++) { baseA[t] = T; T += tot[t]; }
    float invT = 1.f / T;

#pragma unroll
    for (int t = 0; t < 4; t++) {
        float run = baseA[t] + excl[t];
#pragma unroll
        for (int l = 0; l < 4; l++) {
            run += e[t][l];
            int j = 4 * lane + 128 * t + l;
            float suf  = fmaxf(T - run, 0.f);
            float dist = sqrtf(fmaxf(suf * invT * (float)(i - j), 0.f));
            float tmp  = __expf(dist * gam);
            tmp = fminf(fmaxf(tmp, 1e-5f), 1e5f);
            sc[t][l] = (j < i) ? sc[t][l] * tmp : NEG_INF;
        }
    }

    float m2 = NEG_INF;
#pragma unroll
    for (int t = 0; t < 4; t++)
#pragma unroll
        for (int l = 0; l < 4; l++) m2 = fmaxf(m2, sc[t][l]);
#pragma unroll
    for (int off = 16; off; off >>= 1)
        m2 = fmaxf(m2, __shfl_xor_sync(0xffffffffu, m2, off));
    float Z = 0.f;
#pragma unroll
    for (int t = 0; t < 4; t++)
#pragma unroll
        for (int l = 0; l < 4; l++) { e[t][l] = __expf(sc[t][l] - m2); Z += e[t][l]; }
#pragma unroll
    for (int off = 16; off; off >>= 1)
        Z += __shfl_xor_sync(0xffffffffu, Z, off);
    float invZ = 1.f / Z;

#pragma unroll
    for (int t = 0; t < 4; t++) {
        float a0 = e[t][0] * invZ, a1 = e[t][1] * invZ;
        float a2 = e[t][2] * invZ, a3 = e[t][3] * invZ;
        float l0, l1, l2, l3;
        uint2 hp; hp.x = pack_hi(a0, a1, l0, l1); hp.y = pack_hi(a2, a3, l2, l3);
        uint2 lp; lp.x = pack_lo(l0, l1);         lp.y = pack_lo(l2, l3);
        int j0 = 4 * (lane + 32 * t);
        *(uint2*)(Ahi + j0)        = hp;
        *(uint2*)(Ahi + APLN + j0) = lp;
    }
}

// ===================== AV batched GEMM (causal K-limit) ===========================
// grid (4 rowT, 128 bh); tile 128x64; per-buf: A hi/lo 20480 + V hi/lo 10240.
#define AV_BUF 30720
#define AV_SMEM 61440

__global__ __launch_bounds__(256, 1) void av_kernel()
{
    extern __shared__ char sm[];
    const uint32_t sbase = smem_to_u32(sm);
    const int bm = blockIdx.x * 128;
    const int bh = blockIdx.y;
    const int b = bh >> 3, h = bh & 7;
    const int tid = threadIdx.x, wid = tid >> 5, lane = tid & 31;
    const int nst = (bm + 128) >> 5;

    uint4 aR[4], vR[2];
    float acc[8][4];
#pragma unroll
    for (int i = 0; i < 8; i++)
#pragma unroll
        for (int j = 0; j < 4; j++) acc[i][j] = 0.f;

    auto loadA = [&](int s) {
#pragma unroll
        for (int it = 0; it < 4; it++) {
            int idx = it * 256 + tid;
            int pl = idx >> 9, r = (idx >> 2) & 127, c = idx & 3;
            aR[it] = *(const uint4*)(g_A + (size_t)pl * APLN +
                         ((size_t)bh * 512 + bm + r) * 512 + s * 32 + c * 8);
        }
    };
    auto loadV = [&](int s) {
#pragma unroll
        for (int it = 0; it < 2; it++) {
            int idx = it * 256 + tid;
            int pl = idx >> 8, d = (idx >> 2) & 63, c = idx & 3;
            vR[it] = *(const uint4*)(g_Vtb + (size_t)pl * QKVPLN +
                         ((size_t)bh * 64 + d) * 512 + s * 32 + c * 8);
        }
    };
    auto storeAV = [&](int buf) {
        char* base = sm + buf * AV_BUF;
#pragma unroll
        for (int it = 0; it < 4; it++) {
            int idx = it * 256 + tid;
            int pl = idx >> 9, r = (idx >> 2) & 127, c = idx & 3;
            *(uint4*)(base + pl * 10240 + r * 80 + c * 16) = aR[it];
        }
#pragma unroll
        for (int it = 0; it < 2; it++) {
            int idx = it * 256 + tid;
            int pl = idx >> 8, d = (idx >> 2) & 63, c = idx & 3;
            *(uint4*)(base + 20480 + pl * 5120 + d * 80 + c * 16) = vR[it];
        }
    };

    const int wm = (wid >> 1) * 32, wn = (wid & 1) * 32;
    const int aoff   = (lane & 15) * 80 + (lane >> 4) * 16;
    const int boff_n = ((lane >> 4) << 3) + (lane & 7);
    const int bsel   = ((lane >> 3) & 1) * 16;

    auto compute = [&](int buf) {
        uint32_t Ab = sbase + buf * AV_BUF;
        uint32_t Vb = Ab + 20480;
#pragma unroll
        for (int kh = 0; kh < 2; kh++) {
            uint32_t bh_[8], bl_[8], a[8];
#pragma unroll
            for (int nf2 = 0; nf2 < 2; nf2++) {
                uint32_t baddr = Vb + (wn + nf2 * 16 + boff_n) * 80 + kh * 32 + bsel;
                ldsm4(bh_ + nf2 * 4, baddr);
                ldsm4(bl_ + nf2 * 4, baddr + 5120);
            }
#pragma unroll
            for (int mf = 0; mf < 2; mf++)
                ldsm4(a + mf * 4, Ab + (wm + mf * 16) * 80 + kh * 32 + aoff);
#pragma unroll
            for (int mf = 0; mf < 2; mf++)
#pragma unroll
                for (int nf = 0; nf < 4; nf++)
                    mma16816(acc[mf * 4 + nf], a + mf * 4, bh_ + nf * 2);
#pragma unroll
            for (int mf = 0; mf < 2; mf++)
#pragma unroll
                for (int nf = 0; nf < 4; nf++)
                    mma16816(acc[mf * 4 + nf], a + mf * 4, bl_ + nf * 2);
#pragma unroll
            for (int mf = 0; mf < 2; mf++)
                ldsm4(a + mf * 4, Ab + 10240 + (wm + mf * 16) * 80 + kh * 32 + aoff);
#pragma unroll
            for (int mf = 0; mf < 2; mf++)
#pragma unroll
                for (int nf = 0; nf < 4; nf++)
                    mma16816(acc[mf * 4 + nf], a + mf * 4, bh_ + nf * 2);
        }
    };

    loadA(0); loadV(0);
    storeAV(0);
    __syncthreads();
    for (int s = 0; s < nst; s++) {
        if (s + 1 < nst) { loadA(s + 1); loadV(s + 1); }
        compute(s & 1);
        if (s + 1 < nst) {
            storeAV((s + 1) & 1);
            __syncthreads();
        }
    }

#pragma unroll
    for (int mf = 0; mf < 2; mf++)
#pragma unroll
        for (int nf = 0; nf < 4; nf++) {
            float* cc = acc[mf * 4 + nf];
            int col = wn + nf * 8 + (lane & 3) * 2;
#pragma unroll
            for (int rp = 0; rp < 2; rp++) {
                int mrow = bm + wm + mf * 16 + (lane >> 2) + rp * 8;
                *(float2*)(g_X + ((size_t)(b * 512 + mrow)) * 512 + h * 64 + col) =
                    make_float2(cc[rp * 2], cc[rp * 2 + 1]);
            }
        }
}

// ===================== norm01 stats =====================
__global__ void stats_kernel(const int* __restrict__ sgap, const int* __restrict__ pcount)
{
    __shared__ float sh[128];
    float s0 = 0, q0 = 0, s1 = 0, q1 = 0;
    for (int idx = threadIdx.x; idx < MTOT; idx += 1024) {
        float a = (float)sgap[idx];   s0 += a; q0 += a*a;
        float b = (float)pcount[idx]; s1 += b; q1 += b*b;
    }
#pragma unroll
    for (int off = 16; off; off >>= 1) {
        s0 += __shfl_xor_sync(0xffffffffu, s0, off);
        q0 += __shfl_xor_sync(0xffffffffu, q0, off);
        s1 += __shfl_xor_sync(0xffffffffu, s1, off);
        q1 += __shfl_xor_sync(0xffffffffu, q1, off);
    }
    int wd = threadIdx.x >> 5, ln = threadIdx.x & 31;
    if (ln == 0) { sh[wd] = s0; sh[32+wd] = q0; sh[64+wd] = s1; sh[96+wd] = q1; }
    __syncthreads();
    if (threadIdx.x == 0) {
        float S0=0,Q0=0,S1=0,Q1=0;
        for (int i = 0; i < 32; i++) { S0+=sh[i]; Q0+=sh[32+i]; S1+=sh[64+i]; Q1+=sh[96+i]; }
        float n = (float)MTOT;
        float m0 = S0 / n, m1 = S1 / n;
        float v0 = (Q0 - n*m0*m0) / (n - 1.f);
        float v1 = (Q1 - n*m1*m1) / (n - 1.f);
        g_stats[0] = m0; g_stats[1] = 1.f / (sqrtf(fmaxf(v0, 0.f)) + 1e-6f);
        g_stats[2] = m1; g_stats[3] = 1.f / (sqrtf(fmaxf(v1, 0.f)) + 1e-6f);
    }
}

// ===================== interference hidden layer =====================
__global__ __launch_bounds__(256) void hidden_kernel(
    const int* __restrict__ sgap, const int* __restrict__ pcount,
    const float* __restrict__ Wi1, const float* __restrict__ bi1)
{
    int idx = blockIdx.x * 256 + threadIdx.x;
    int r = idx >> 7, mcol = idx & 127;
    float ii0 = 0.5f * (tanhf(((float)sgap[r]   - g_stats[0]) * g_stats[1]) + 1.f);
    float ii1 = 0.5f * (tanhf(((float)pcount[r] - g_stats[2]) * g_stats[3]) + 1.f);
    float hv = ii0 * Wi1[2*mcol] + ii1 * Wi1[2*mcol + 1] + bi1[mcol];
    g_H[idx] = fmaxf(hv, 0.f);
}

// ===================== layernorm =====================
__global__ __launch_bounds__(128) void ln_kernel(
    const float* __restrict__ gw, const float* __restrict__ bw)
{
    int r = blockIdx.x, t = threadIdx.x;
    __shared__ float red[8];
    float4 v = ((const float4*)(g_Y + (size_t)r * DM))[t];
    float s = v.x + v.y + v.z + v.w;
#pragma unroll
    for (int off = 16; off; off >>= 1) s += __shfl_xor_sync(0xffffffffu, s, off);
    int wd = t >> 5, ln = t & 31;
    if (ln == 0) red[wd] = s;
    __syncthreads();
    float mu = (red[0] + red[1] + red[2] + red[3]) * (1.f / 512.f);
    float dx = v.x - mu, dy = v.y - mu, dz = v.z - mu, dw = v.w - mu;
    float ss = dx*dx + dy*dy + dz*dz + dw*dw;
#pragma unroll
    for (int off = 16; off; off >>= 1) ss += __shfl_xor_sync(0xffffffffu, ss, off);
    if (ln == 0) red[4 + wd] = ss;
    __syncthreads();
    float var  = (red[4] + red[5] + red[6] + red[7]) * (1.f / 512.f);
    float rstd = rsqrtf(var + 1e-5f);
    float4 gg = ((const float4*)gw)[t];
    float4 bb = ((const float4*)bw)[t];
    float4 o;
    o.x = dx * rstd * gg.x + bb.x;
    o.y = dy * rstd * gg.y + bb.y;
    o.z = dz * rstd * gg.z + bb.z;
    o.w = dw * rstd * gg.w + bb.w;
    ((float4*)(g_Y + (size_t)r * DM))[t] = o;
}

// ===================== launcher =====================
extern "C" void kernel_launch(void* const* d_in, const int* in_sizes, int n_in,
                              void* d_out, int out_size)
{
    const float* q      = (const float*)d_in[0];
    const float* k      = (const float*)d_in[1];
    const float* v      = (const float*)d_in[2];
    const int*   sgap   = (const int*)d_in[3];
    const int*   pcount = (const int*)d_in[4];
    const float* Wq = (const float*)d_in[5];  const float* bq = (const float*)d_in[6];
    const float* Wk = (const float*)d_in[7];  const float* bk = (const float*)d_in[8];
    const float* Wv = (const float*)d_in[9];  const float* bv = (const float*)d_in[10];
    const float* Wo = (const float*)d_in[11]; const float* bo = (const float*)d_in[12];
    const float* gammas = (const float*)d_in[13];
    const float* ln_g = (const float*)d_in[14]; const float* ln_b = (const float*)d_in[15];
    const float* Wi1 = (const float*)d_in[16];  const float* bi1 = (const float*)d_in[17];
    const float* Wi2 = (const float*)d_in[18];  const float* bi2 = (const float*)d_in[19];
    const float* iscale = (const float*)d_in[20];
    float* out = (float*)d_out;

    float *X, *Y, *Hb;
    __nv_bfloat16 *Qb, *Kb, *Vtb;
    unsigned char* Wpk;
    cudaGetSymbolAddress((void**)&X,   g_X);
    cudaGetSymbolAddress((void**)&Y,   g_Y);
    cudaGetSymbolAddress((void**)&Hb,  g_H);
    cudaGetSymbolAddress((void**)&Qb,  g_Qb);
    cudaGetSymbolAddress((void**)&Kb,  g_Kb);
    cudaGetSymbolAddress((void**)&Vtb, g_Vtb);
    cudaGetSymbolAddress((void**)&Wpk, g_Wpk);

    cudaFuncSetAttribute(tgemm_kernel<0>, cudaFuncAttributeMaxDynamicSharedMemorySize, TG2_SMEM);
    cudaFuncSetAttribute(tgemm_kernel<3>, cudaFuncAttributeMaxDynamicSharedMemorySize, TG2_SMEM);
    cudaFuncSetAttribute(tgemm_kernel<4>, cudaFuncAttributeMaxDynamicSharedMemorySize, TG2_SMEM);
    cudaFuncSetAttribute(tgemm_kernel<5>, cudaFuncAttributeMaxDynamicSharedMemorySize, TG2_SMEM);
    cudaFuncSetAttribute(tgemm_kernel<6>, cudaFuncAttributeMaxDynamicSharedMemorySize, TG2_SMEM);
    cudaFuncSetAttribute(qk_kernel, cudaFuncAttributeMaxDynamicSharedMemorySize, SK_SMEM);
    cudaFuncSetAttribute(av_kernel, cudaFuncAttributeMaxDynamicSharedMemorySize, AV_SMEM);

    wconv_all<<<2176, 256>>>(Wq, Wk, Wv, Wo, Wi2, Wpk);

    dim3 gg(4, 64);
    tgemm_kernel<4><<<gg, 256, TG2_SMEM>>>(q, Wpk + 0u*1048576u, bq, nullptr, Qb,  DM, DM, 262144, nullptr, nullptr);
    tgemm_kernel<5><<<gg, 256, TG2_SMEM>>>(k, Wpk + 1u*1048576u, bk, nullptr, Kb,  DM, DM, 262144, nullptr, nullptr);
    tgemm_kernel<6><<<gg, 256, TG2_SMEM>>>(v, Wpk + 2u*1048576u, bv, nullptr, Vtb, DM, DM, 262144, nullptr, nullptr);

    stats_kernel<<<1, 1024>>>(sgap, pcount);

    qk_kernel<<<dim3(4, 4, 128), 256, SK_SMEM>>>();
    row_kernel<<<dim3(64, 128), 256>>>(gammas);
    av_kernel<<<dim3(4, 128), 256, AV_SMEM>>>();

    hidden_kernel<<<(MTOT*128)/256, 256>>>(sgap, pcount, Wi1, bi1);
    tgemm_kernel<3><<<gg, 256, TG2_SMEM>>>(Hb, Wpk + 4u*1048576u, bi2, Y, nullptr, DM, 128, 65536, X, iscale);

    ln_kernel<<<MTOT, 128>>>(ln_g, ln_b);

    tgemm_kernel<0><<<gg, 256, TG2_SMEM>>>(Y, Wpk + 3u*1048576u, bo, out, nullptr, DM, DM, 262144, nullptr, nullptr);
}